// round 7
// baseline (speedup 1.0000x reference)
#include <cuda_runtime.h>
#include <cuda_bf16.h>
#include <cstdint>

#define DIM 1024
#define S_LEN 4096
#define NH 16
#define HD 64

// Scratch (allocation-free rule: __device__ globals)
__device__ __nv_bfloat16 g_Qh[S_LEN * DIM];
__device__ __nv_bfloat16 g_Ql[S_LEN * DIM];
__device__ __nv_bfloat16 g_Kh[S_LEN * DIM];
__device__ __nv_bfloat16 g_Kl[S_LEN * DIM];
__device__ __nv_bfloat16 g_Vh[S_LEN * DIM];
__device__ __nv_bfloat16 g_Vl[S_LEN * DIM];
__device__ float g_Z[S_LEN * DIM];

// ===========================================================================
// Base-ISA tensor-core helpers (compute_103-safe: ldmatrix + mma.sync)
// ===========================================================================
__device__ __forceinline__ uint32_t smem_u32(const void* p) {
    uint32_t a;
    asm("{ .reg .u64 t; cvta.to.shared.u64 t, %1; cvt.u32.u64 %0, t; }"
        : "=r"(a) : "l"(p));
    return a;
}

__device__ __forceinline__ void ldm_x4(uint32_t* f, uint32_t addr) {
    asm volatile("ldmatrix.sync.aligned.m8n8.x4.shared.b16 {%0,%1,%2,%3}, [%4];"
                 : "=r"(f[0]), "=r"(f[1]), "=r"(f[2]), "=r"(f[3]) : "r"(addr));
}
__device__ __forceinline__ void ldm_x4t(uint32_t* f, uint32_t addr) {
    asm volatile("ldmatrix.sync.aligned.m8n8.x4.trans.shared.b16 {%0,%1,%2,%3}, [%4];"
                 : "=r"(f[0]), "=r"(f[1]), "=r"(f[2]), "=r"(f[3]) : "r"(addr));
}
__device__ __forceinline__ void ldm_x2(uint32_t* f, uint32_t addr) {
    asm volatile("ldmatrix.sync.aligned.m8n8.x2.shared.b16 {%0,%1}, [%2];"
                 : "=r"(f[0]), "=r"(f[1]) : "r"(addr));
}
__device__ __forceinline__ void mma_bf16(float* c, const uint32_t* a,
                                         const uint32_t* b) {
    asm volatile(
        "mma.sync.aligned.m16n8k16.row.col.f32.bf16.bf16.f32 "
        "{%0,%1,%2,%3}, {%4,%5,%6,%7}, {%8,%9}, {%0,%1,%2,%3};"
        : "+f"(c[0]), "+f"(c[1]), "+f"(c[2]), "+f"(c[3])
        : "r"(a[0]), "r"(a[1]), "r"(a[2]), "r"(a[3]), "r"(b[0]), "r"(b[1]));
}

__device__ __forceinline__ uint32_t pack_bf16x2(float x, float y) {
    __nv_bfloat162 p;
    p.x = __float2bfloat16(x);
    p.y = __float2bfloat16(y);
    return *(uint32_t*)&p;
}
__device__ __forceinline__ uint32_t pack_lo(float x, float y, uint32_t hi) {
    __nv_bfloat162 h = *(__nv_bfloat162*)&hi;
    return pack_bf16x2(x - __bfloat162float(h.x), y - __bfloat162float(h.y));
}

#define CP_ASYNC16(dst, src)                                                   \
    asm volatile("cp.async.cg.shared.global [%0], [%1], 16;"                   \
                 :: "r"(dst), "l"(src))
#define CP_COMMIT() asm volatile("cp.async.commit_group;" ::: "memory")
#define CP_WAIT0()  asm volatile("cp.async.wait_group 0;" ::: "memory")

// ===========================================================================
// Split-bf16 tensor GEMM-NT body:  C = A * B^T  (A,B fp32 row-major)
// Output: fp32 C, or split-bf16 (Chi, Clo) with scale folded in.
// ===========================================================================
#define RS 40
#define SEG (128 * RS)
#define STAGE_ELEMS (4 * SEG)
#define STAGE_BYTES (STAGE_ELEMS * 2)
#define GEMM_SMEM (2 * STAGE_BYTES)

__device__ __forceinline__
void gemm_body(const float* __restrict__ A, const float* __restrict__ B,
               float* __restrict__ C, __nv_bfloat16* __restrict__ Chi,
               __nv_bfloat16* __restrict__ Clo, float scale,
               int M, int N, int Kd, __nv_bfloat16* smem) {
    const uint32_t sb = smem_u32(smem);
    const int t    = threadIdx.x;
    const int lane = t & 31;
    const int wid  = t >> 5;
    const int wm   = (wid >> 2) * 64;
    const int wn   = (wid & 3) * 32;
    const int bm   = blockIdx.y * 128;
    const int bn   = blockIdx.x * 128;

    float acc[4][4][4] = {};
    float4 pa[4], pb[4];

    auto gload = [&](int k0) {
#pragma unroll
        for (int i = 0; i < 4; i++) {
            int id  = t + i * 256;
            int row = id >> 3;
            int col = (id & 7) * 4;
            pa[i] = *(const float4*)(A + (size_t)(bm + row) * Kd + k0 + col);
            pb[i] = *(const float4*)(B + (size_t)(bn + row) * Kd + k0 + col);
        }
    };

    auto sstore = [&](int stage) {
        __nv_bfloat16* base = smem + stage * STAGE_ELEMS;
#pragma unroll
        for (int i = 0; i < 4; i++) {
            int id  = t + i * 256;
            int row = id >> 3;
            int col = (id & 7) * 4;
            int off = row * RS + col;
            float4 va = pa[i];
            float4 vb = pb[i];
            uint32_t ah0 = pack_bf16x2(va.x, va.y);
            uint32_t ah1 = pack_bf16x2(va.z, va.w);
            uint32_t al0 = pack_lo(va.x, va.y, ah0);
            uint32_t al1 = pack_lo(va.z, va.w, ah1);
            uint32_t bh0 = pack_bf16x2(vb.x, vb.y);
            uint32_t bh1 = pack_bf16x2(vb.z, vb.w);
            uint32_t bl0 = pack_lo(vb.x, vb.y, bh0);
            uint32_t bl1 = pack_lo(vb.z, vb.w, bh1);
            *(uint2*)(base + 0 * SEG + off) = make_uint2(ah0, ah1);
            *(uint2*)(base + 1 * SEG + off) = make_uint2(al0, al1);
            *(uint2*)(base + 2 * SEG + off) = make_uint2(bh0, bh1);
            *(uint2*)(base + 3 * SEG + off) = make_uint2(bl0, bl1);
        }
    };

    const int nchunks = Kd / 32;
    gload(0);
    sstore(0);
    __syncthreads();

    for (int c = 0; c < nchunks; c++) {
        const int stage = c & 1;
        if (c + 1 < nchunks) gload((c + 1) * 32);

        const uint32_t sstage = sb + stage * STAGE_BYTES;
        const uint32_t a_base =
            sstage + ((wm + (lane & 15)) * RS + (lane >> 4) * 8) * 2;
        const uint32_t b_base =
            sstage + 2 * SEG * 2 +
            ((wn + (lane & 7)) * RS + (((lane & 15) >> 3) * 8)) * 2;

#pragma unroll
        for (int ks = 0; ks < 2; ks++) {
            uint32_t ah[4][4], al[4][4], bh[4][2], bl[4][2];
#pragma unroll
            for (int mt = 0; mt < 4; mt++) {
                uint32_t addr = a_base + (mt * 16 * RS + ks * 16) * 2;
                ldm_x4(ah[mt], addr);
                ldm_x4(al[mt], addr + SEG * 2);
            }
#pragma unroll
            for (int nt = 0; nt < 4; nt++) {
                uint32_t addr = b_base + (nt * 8 * RS + ks * 16) * 2;
                ldm_x2(bh[nt], addr);
                ldm_x2(bl[nt], addr + SEG * 2);
            }
#pragma unroll
            for (int mt = 0; mt < 4; mt++)
#pragma unroll
                for (int nt = 0; nt < 4; nt++) {
                    mma_bf16(acc[mt][nt], ah[mt], bh[nt]);
                    mma_bf16(acc[mt][nt], ah[mt], bl[nt]);
                    mma_bf16(acc[mt][nt], al[mt], bh[nt]);
                }
        }
        __syncthreads();
        if (c + 1 < nchunks) {
            sstore(stage ^ 1);
            __syncthreads();
        }
    }

    const int r0 = bm + wm + (lane >> 2);
    const int c0 = bn + wn + (lane & 3) * 2;
    if (C) {
#pragma unroll
        for (int mt = 0; mt < 4; mt++)
#pragma unroll
            for (int nt = 0; nt < 4; nt++) {
                float* d0 = C + (size_t)(r0 + mt * 16) * N + c0 + nt * 8;
                float* d1 = d0 + 8 * N;
                *(float2*)d0 = make_float2(acc[mt][nt][0], acc[mt][nt][1]);
                *(float2*)d1 = make_float2(acc[mt][nt][2], acc[mt][nt][3]);
            }
    } else {
#pragma unroll
        for (int mt = 0; mt < 4; mt++)
#pragma unroll
            for (int nt = 0; nt < 4; nt++) {
                float v0 = acc[mt][nt][0] * scale;
                float v1 = acc[mt][nt][1] * scale;
                float v2 = acc[mt][nt][2] * scale;
                float v3 = acc[mt][nt][3] * scale;
                uint32_t h01 = pack_bf16x2(v0, v1);
                uint32_t l01 = pack_lo(v0, v1, h01);
                uint32_t h23 = pack_bf16x2(v2, v3);
                uint32_t l23 = pack_lo(v2, v3, h23);
                size_t o0 = (size_t)(r0 + mt * 16) * N + c0 + nt * 8;
                size_t o1 = o0 + (size_t)8 * N;
                *(uint32_t*)(Chi + o0) = h01;
                *(uint32_t*)(Clo + o0) = l01;
                *(uint32_t*)(Chi + o1) = h23;
                *(uint32_t*)(Clo + o1) = l23;
            }
    }
}

// Fused QKV projection: blockIdx.z selects Wq/Wk/Wv -> (hi,lo) outputs.
__global__ __launch_bounds__(256, 1)
void qkv_gemm(const float* __restrict__ x,
              const float* __restrict__ Wq, const float* __restrict__ Wk,
              const float* __restrict__ Wv,
              __nv_bfloat16* __restrict__ Qh, __nv_bfloat16* __restrict__ Ql,
              __nv_bfloat16* __restrict__ Kh, __nv_bfloat16* __restrict__ Kl,
              __nv_bfloat16* __restrict__ Vh, __nv_bfloat16* __restrict__ Vl) {
    extern __shared__ __nv_bfloat16 smem[];
    const int z = blockIdx.z;
    const float* B = (z == 0) ? Wq : (z == 1) ? Wk : Wv;
    __nv_bfloat16* Chi = (z == 0) ? Qh : (z == 1) ? Kh : Vh;
    __nv_bfloat16* Clo = (z == 0) ? Ql : (z == 1) ? Kl : Vl;
    float scale = (z == 0) ? 0.125f : 1.0f;
    gemm_body(x, B, nullptr, Chi, Clo, scale, S_LEN, DIM, DIM, smem);
}

// Output projection (fp32 out).
__global__ __launch_bounds__(256, 1)
void out_gemm(const float* __restrict__ A, const float* __restrict__ B,
              float* __restrict__ C) {
    extern __shared__ __nv_bfloat16 smem[];
    gemm_body(A, B, C, nullptr, nullptr, 1.0f, S_LEN, DIM, DIM, smem);
}

// ===========================================================================
// Tensor-core causal flash attention, pre-split bf16 inputs, cp.async
// double-buffered K/V, Q fragments reloaded per tile (register relief),
// 2 CTAs/SM forced via launch_bounds.
// CTA = 128 q rows x 1 head; 8 warps x 16 rows.
// smem rows (RS2=72 bf16 each):
//   [0..127] Qhi  [128..255] Qlo
//   stage s at 256+s*256:  Khi(64) Klo(64) Vhi(64) Vlo(64)
// ===========================================================================
#define RS2 72
#define ATTN_SMEM (768 * RS2 * 2)   // 110592 bytes

__global__ __launch_bounds__(256, 2)
void attn_mma(const __nv_bfloat16* __restrict__ Qh,
              const __nv_bfloat16* __restrict__ Ql,
              const __nv_bfloat16* __restrict__ Kh,
              const __nv_bfloat16* __restrict__ Kl,
              const __nv_bfloat16* __restrict__ Vh,
              const __nv_bfloat16* __restrict__ Vl,
              float* __restrict__ Z) {
    extern __shared__ __nv_bfloat16 sm[];
    const uint32_t sb = smem_u32(sm);
    const int qb   = (int)gridDim.x - 1 - (int)blockIdx.x;  // big tiles first
    const int h    = blockIdx.y;
    const int t    = threadIdx.x;
    const int lane = t & 31;
    const int w    = t >> 5;

    auto issue_kv = [&](int kb, int s) {
        const __nv_bfloat16* bases[4] = {Kh, Kl, Vh, Vl};
        const int r_lo = t >> 3;
        const int c8   = (t & 7) * 8;
#pragma unroll
        for (int i = 0; i < 8; i++) {
            int mtx = i >> 1;
            int r   = (i & 1) * 32 + r_lo;
            const __nv_bfloat16* src =
                bases[mtx] + (size_t)(kb * 64 + r) * DIM + h * 64 + c8;
            uint32_t dst =
                sb + ((256 + s * 256 + mtx * 64 + r) * RS2 + c8) * 2;
            CP_ASYNC16(dst, src);
        }
    };

    // ---- prologue: Q (hi+lo) + stage 0 K/V ----
    {
        const int c8 = (t & 7) * 8;
#pragma unroll
        for (int i = 0; i < 8; i++) {
            int id  = t + i * 256;
            int buf = id >> 10;
            int r   = (id & 1023) >> 3;
            const __nv_bfloat16* src =
                (buf ? Ql : Qh) + (size_t)(qb * 128 + r) * DIM + h * 64 + c8;
            uint32_t dst = sb + ((buf * 128 + r) * RS2 + c8) * 2;
            CP_ASYNC16(dst, src);
        }
        issue_kv(0, 0);
        CP_COMMIT();
        CP_WAIT0();
    }
    __syncthreads();

    const uint32_t q_base =
        sb + ((w * 16 + (lane & 15)) * RS2 + (lane >> 4) * 8) * 2;

    float o[8][4] = {};
    float m0 = -1e30f, m1 = -1e30f, l0 = 0.f, l1 = 0.f;
    const int row0 = qb * 128 + w * 16 + (lane >> 2);

    const int nkb = 2 * qb + 2;
    for (int kb = 0; kb < nkb; kb++) {
        const int s = kb & 1;
        if (kb + 1 < nkb) { issue_kv(kb + 1, s ^ 1); CP_COMMIT(); }

        const bool active = (kb * 64 <= qb * 128 + w * 16 + 15);
        if (active) {
            const int KB = 256 + s * 256;        // Khi rows
            const int VB = KB + 128;             // Vhi rows

            // ---- S = Q K^T (3-pass split; Q frags reloaded per ks) ----
            float c[8][4] = {};
#pragma unroll
            for (int ks = 0; ks < 4; ks++) {
                uint32_t qh[4], ql4[4];
                ldm_x4(qh,  q_base + ks * 32);
                ldm_x4(ql4, q_base + ks * 32 + 128 * RS2 * 2);
#pragma unroll
                for (int ntp = 0; ntp < 4; ntp++) {
                    uint32_t fh[4], fl[4];
                    uint32_t addr = sb +
                        ((KB + ntp * 16 + (lane & 15)) * RS2 +
                         ks * 16 + (lane >> 4) * 8) * 2;
                    ldm_x4(fh, addr);
                    ldm_x4(fl, addr + 64 * RS2 * 2);
                    uint32_t beh[2] = {fh[0], fh[2]}, bel[2] = {fl[0], fl[2]};
                    uint32_t boh[2] = {fh[1], fh[3]}, bol[2] = {fl[1], fl[3]};
                    mma_bf16(c[2 * ntp],     qh,  beh);
                    mma_bf16(c[2 * ntp],     qh,  bel);
                    mma_bf16(c[2 * ntp],     ql4, beh);
                    mma_bf16(c[2 * ntp + 1], qh,  boh);
                    mma_bf16(c[2 * ntp + 1], qh,  bol);
                    mma_bf16(c[2 * ntp + 1], ql4, boh);
                }
            }

            // ---- causal mask (near-diagonal blocks only) ----
            if (kb * 64 + 63 > row0) {
                const int colbase = kb * 64 + (lane & 3) * 2;
#pragma unroll
                for (int nt = 0; nt < 8; nt++) {
                    int cc = colbase + nt * 8;
                    if (cc     > row0)     c[nt][0] = -1e30f;
                    if (cc + 1 > row0)     c[nt][1] = -1e30f;
                    if (cc     > row0 + 8) c[nt][2] = -1e30f;
                    if (cc + 1 > row0 + 8) c[nt][3] = -1e30f;
                }
            }

            // ---- online softmax ----
            float mx0 = -1e30f, mx1 = -1e30f;
#pragma unroll
            for (int nt = 0; nt < 8; nt++) {
                mx0 = fmaxf(mx0, fmaxf(c[nt][0], c[nt][1]));
                mx1 = fmaxf(mx1, fmaxf(c[nt][2], c[nt][3]));
            }
            mx0 = fmaxf(mx0, __shfl_xor_sync(0xffffffffu, mx0, 1));
            mx0 = fmaxf(mx0, __shfl_xor_sync(0xffffffffu, mx0, 2));
            mx1 = fmaxf(mx1, __shfl_xor_sync(0xffffffffu, mx1, 1));
            mx1 = fmaxf(mx1, __shfl_xor_sync(0xffffffffu, mx1, 2));
            float M0 = fmaxf(m0, mx0);
            float M1 = fmaxf(m1, mx1);
            float sc0 = __expf(m0 - M0);
            float sc1 = __expf(m1 - M1);
            m0 = M0; m1 = M1;
            float s0 = 0.f, s1 = 0.f;
#pragma unroll
            for (int nt = 0; nt < 8; nt++) {
                c[nt][0] = __expf(c[nt][0] - M0);
                c[nt][1] = __expf(c[nt][1] - M0);
                c[nt][2] = __expf(c[nt][2] - M1);
                c[nt][3] = __expf(c[nt][3] - M1);
                s0 += c[nt][0] + c[nt][1];
                s1 += c[nt][2] + c[nt][3];
            }
            s0 += __shfl_xor_sync(0xffffffffu, s0, 1);
            s0 += __shfl_xor_sync(0xffffffffu, s0, 2);
            s1 += __shfl_xor_sync(0xffffffffu, s1, 1);
            s1 += __shfl_xor_sync(0xffffffffu, s1, 2);
            l0 = l0 * sc0 + s0;
            l1 = l1 * sc1 + s1;
#pragma unroll
            for (int nt = 0; nt < 8; nt++) {
                o[nt][0] *= sc0; o[nt][1] *= sc0;
                o[nt][2] *= sc1; o[nt][3] *= sc1;
            }

            // ---- O += P V (3-pass split; P packed from registers) ----
#pragma unroll
            for (int ks = 0; ks < 4; ks++) {
                uint32_t ah[4], al[4];
                ah[0] = pack_bf16x2(c[2 * ks][0],     c[2 * ks][1]);
                ah[1] = pack_bf16x2(c[2 * ks][2],     c[2 * ks][3]);
                ah[2] = pack_bf16x2(c[2 * ks + 1][0], c[2 * ks + 1][1]);
                ah[3] = pack_bf16x2(c[2 * ks + 1][2], c[2 * ks + 1][3]);
                al[0] = pack_lo(c[2 * ks][0],     c[2 * ks][1],     ah[0]);
                al[1] = pack_lo(c[2 * ks][2],     c[2 * ks][3],     ah[1]);
                al[2] = pack_lo(c[2 * ks + 1][0], c[2 * ks + 1][1], ah[2]);
                al[3] = pack_lo(c[2 * ks + 1][2], c[2 * ks + 1][3], ah[3]);
#pragma unroll
                for (int ntp = 0; ntp < 4; ntp++) {
                    uint32_t fh[4], fl[4];
                    uint32_t addr = sb +
                        ((VB + ks * 16 + (lane & 15)) * RS2 +
                         ntp * 16 + (lane >> 4) * 8) * 2;
                    ldm_x4t(fh, addr);
                    ldm_x4t(fl, addr + 64 * RS2 * 2);
                    uint32_t veh[2] = {fh[0], fh[1]}, vel[2] = {fl[0], fl[1]};
                    uint32_t voh[2] = {fh[2], fh[3]}, vol[2] = {fl[2], fl[3]};
                    mma_bf16(o[2 * ntp],     ah, veh);
                    mma_bf16(o[2 * ntp],     ah, vel);
                    mma_bf16(o[2 * ntp],     al, veh);
                    mma_bf16(o[2 * ntp + 1], ah, voh);
                    mma_bf16(o[2 * ntp + 1], ah, vol);
                    mma_bf16(o[2 * ntp + 1], al, voh);
                }
            }
        }
        if (kb + 1 < nkb) CP_WAIT0();
        __syncthreads();
    }

    // ---- normalize + store ----
    const float inv0 = 1.0f / l0;
    const float inv1 = 1.0f / l1;
    float* z0 = Z + (size_t)row0 * DIM + h * HD + (lane & 3) * 2;
#pragma unroll
    for (int nt = 0; nt < 8; nt++) {
        *(float2*)(z0 + nt * 8) =
            make_float2(o[nt][0] * inv0, o[nt][1] * inv0);
        *(float2*)(z0 + (size_t)8 * DIM + nt * 8) =
            make_float2(o[nt][2] * inv1, o[nt][3] * inv1);
    }
}

// ===========================================================================
extern "C" void kernel_launch(void* const* d_in, const int* in_sizes, int n_in,
                              void* d_out, int out_size) {
    const float* x  = (const float*)d_in[0];
    const float* Wq = (const float*)d_in[1];
    const float* Wk = (const float*)d_in[2];
    const float* Wv = (const float*)d_in[3];
    const float* Wo = (const float*)d_in[4];
    float* out = (float*)d_out;

    __nv_bfloat16 *dQh, *dQl, *dKh, *dKl, *dVh, *dVl;
    float* dZ;
    cudaGetSymbolAddress((void**)&dQh, g_Qh);
    cudaGetSymbolAddress((void**)&dQl, g_Ql);
    cudaGetSymbolAddress((void**)&dKh, g_Kh);
    cudaGetSymbolAddress((void**)&dKl, g_Kl);
    cudaGetSymbolAddress((void**)&dVh, g_Vh);
    cudaGetSymbolAddress((void**)&dVl, g_Vl);
    cudaGetSymbolAddress((void**)&dZ, g_Z);

    cudaFuncSetAttribute(qkv_gemm,
                         cudaFuncAttributeMaxDynamicSharedMemorySize, GEMM_SMEM);
    cudaFuncSetAttribute(out_gemm,
                         cudaFuncAttributeMaxDynamicSharedMemorySize, GEMM_SMEM);
    cudaFuncSetAttribute(attn_mma,
                         cudaFuncAttributeMaxDynamicSharedMemorySize, ATTN_SMEM);

    qkv_gemm<<<dim3(DIM / 128, S_LEN / 128, 3), 256, GEMM_SMEM>>>(
        x, Wq, Wk, Wv, dQh, dQl, dKh, dKl, dVh, dVl);

    attn_mma<<<dim3(S_LEN / 128, NH), 256, ATTN_SMEM>>>(dQh, dQl, dKh, dKl,
                                                        dVh, dVl, dZ);

    out_gemm<<<dim3(DIM / 128, S_LEN / 128), 256, GEMM_SMEM>>>(dZ, Wo, out);
}

// round 8
// speedup vs baseline: 1.0400x; 1.0400x over previous
#include <cuda_runtime.h>
#include <cuda_bf16.h>
#include <cstdint>

#define DIM 1024
#define S_LEN 4096
#define NH 16
#define HD 64

// Scratch (allocation-free rule: __device__ globals)
__device__ __nv_bfloat16 g_Qh[S_LEN * DIM];
__device__ __nv_bfloat16 g_Ql[S_LEN * DIM];
__device__ __nv_bfloat16 g_Kh[S_LEN * DIM];
__device__ __nv_bfloat16 g_Kl[S_LEN * DIM];
__device__ __nv_bfloat16 g_Vh[S_LEN * DIM];
__device__ __nv_bfloat16 g_Vl[S_LEN * DIM];
__device__ float g_Z[S_LEN * DIM];

// ===========================================================================
// Base-ISA tensor-core helpers (compute_103-safe: ldmatrix + mma.sync)
// ===========================================================================
__device__ __forceinline__ uint32_t smem_u32(const void* p) {
    uint32_t a;
    asm("{ .reg .u64 t; cvta.to.shared.u64 t, %1; cvt.u32.u64 %0, t; }"
        : "=r"(a) : "l"(p));
    return a;
}

__device__ __forceinline__ void ldm_x4(uint32_t* f, uint32_t addr) {
    asm volatile("ldmatrix.sync.aligned.m8n8.x4.shared.b16 {%0,%1,%2,%3}, [%4];"
                 : "=r"(f[0]), "=r"(f[1]), "=r"(f[2]), "=r"(f[3]) : "r"(addr));
}
__device__ __forceinline__ void ldm_x4t(uint32_t* f, uint32_t addr) {
    asm volatile("ldmatrix.sync.aligned.m8n8.x4.trans.shared.b16 {%0,%1,%2,%3}, [%4];"
                 : "=r"(f[0]), "=r"(f[1]), "=r"(f[2]), "=r"(f[3]) : "r"(addr));
}
__device__ __forceinline__ void ldm_x2(uint32_t* f, uint32_t addr) {
    asm volatile("ldmatrix.sync.aligned.m8n8.x2.shared.b16 {%0,%1}, [%2];"
                 : "=r"(f[0]), "=r"(f[1]) : "r"(addr));
}
__device__ __forceinline__ void mma_bf16(float* c, const uint32_t* a,
                                         const uint32_t* b) {
    asm volatile(
        "mma.sync.aligned.m16n8k16.row.col.f32.bf16.bf16.f32 "
        "{%0,%1,%2,%3}, {%4,%5,%6,%7}, {%8,%9}, {%0,%1,%2,%3};"
        : "+f"(c[0]), "+f"(c[1]), "+f"(c[2]), "+f"(c[3])
        : "r"(a[0]), "r"(a[1]), "r"(a[2]), "r"(a[3]), "r"(b[0]), "r"(b[1]));
}

__device__ __forceinline__ uint32_t pack_bf16x2(float x, float y) {
    __nv_bfloat162 p;
    p.x = __float2bfloat16(x);
    p.y = __float2bfloat16(y);
    return *(uint32_t*)&p;
}
__device__ __forceinline__ uint32_t pack_lo(float x, float y, uint32_t hi) {
    __nv_bfloat162 h = *(__nv_bfloat162*)&hi;
    return pack_bf16x2(x - __bfloat162float(h.x), y - __bfloat162float(h.y));
}

#define CP_ASYNC16(dst, src)                                                   \
    asm volatile("cp.async.cg.shared.global [%0], [%1], 16;"                   \
                 :: "r"(dst), "l"(src))
#define CP_COMMIT() asm volatile("cp.async.commit_group;" ::: "memory")
#define CP_WAIT0()  asm volatile("cp.async.wait_group 0;" ::: "memory")

// ===========================================================================
// Split-bf16 tensor GEMM-NT:  C = A * B^T  (R5 version — known 77us/launch)
// ===========================================================================
#define RS 40
#define SEG (128 * RS)
#define STAGE_ELEMS (4 * SEG)
#define STAGE_BYTES (STAGE_ELEMS * 2)
#define GEMM_SMEM (2 * STAGE_BYTES)

__global__ __launch_bounds__(256, 1)
void gemm_mma128(const float* __restrict__ A, const float* __restrict__ B,
                 float* __restrict__ C, __nv_bfloat16* __restrict__ Chi,
                 __nv_bfloat16* __restrict__ Clo, float scale,
                 int M, int N, int Kd) {
    extern __shared__ __nv_bfloat16 smem[];
    const uint32_t sb = smem_u32(smem);
    const int t    = threadIdx.x;
    const int lane = t & 31;
    const int wid  = t >> 5;
    const int wm   = (wid >> 2) * 64;
    const int wn   = (wid & 3) * 32;
    const int bm   = blockIdx.y * 128;
    const int bn   = blockIdx.x * 128;

    float acc[4][4][4] = {};
    float4 pa[4], pb[4];

    auto gload = [&](int k0) {
#pragma unroll
        for (int i = 0; i < 4; i++) {
            int id  = t + i * 256;
            int row = id >> 3;
            int col = (id & 7) * 4;
            pa[i] = *(const float4*)(A + (size_t)(bm + row) * Kd + k0 + col);
            pb[i] = *(const float4*)(B + (size_t)(bn + row) * Kd + k0 + col);
        }
    };

    auto sstore = [&](int stage) {
        __nv_bfloat16* base = smem + stage * STAGE_ELEMS;
#pragma unroll
        for (int i = 0; i < 4; i++) {
            int id  = t + i * 256;
            int row = id >> 3;
            int col = (id & 7) * 4;
            int off = row * RS + col;
            float4 va = pa[i];
            float4 vb = pb[i];
            uint32_t ah0 = pack_bf16x2(va.x, va.y);
            uint32_t ah1 = pack_bf16x2(va.z, va.w);
            uint32_t al0 = pack_lo(va.x, va.y, ah0);
            uint32_t al1 = pack_lo(va.z, va.w, ah1);
            uint32_t bh0 = pack_bf16x2(vb.x, vb.y);
            uint32_t bh1 = pack_bf16x2(vb.z, vb.w);
            uint32_t bl0 = pack_lo(vb.x, vb.y, bh0);
            uint32_t bl1 = pack_lo(vb.z, vb.w, bh1);
            *(uint2*)(base + 0 * SEG + off) = make_uint2(ah0, ah1);
            *(uint2*)(base + 1 * SEG + off) = make_uint2(al0, al1);
            *(uint2*)(base + 2 * SEG + off) = make_uint2(bh0, bh1);
            *(uint2*)(base + 3 * SEG + off) = make_uint2(bl0, bl1);
        }
    };

    const int nchunks = Kd / 32;
    gload(0);
    sstore(0);
    __syncthreads();

    for (int c = 0; c < nchunks; c++) {
        const int stage = c & 1;
        if (c + 1 < nchunks) gload((c + 1) * 32);

        const uint32_t sstage = sb + stage * STAGE_BYTES;
        const uint32_t a_base =
            sstage + ((wm + (lane & 15)) * RS + (lane >> 4) * 8) * 2;
        const uint32_t b_base =
            sstage + 2 * SEG * 2 +
            ((wn + (lane & 7)) * RS + (((lane & 15) >> 3) * 8)) * 2;

#pragma unroll
        for (int ks = 0; ks < 2; ks++) {
            uint32_t ah[4][4], al[4][4], bh[4][2], bl[4][2];
#pragma unroll
            for (int mt = 0; mt < 4; mt++) {
                uint32_t addr = a_base + (mt * 16 * RS + ks * 16) * 2;
                ldm_x4(ah[mt], addr);
                ldm_x4(al[mt], addr + SEG * 2);
            }
#pragma unroll
            for (int nt = 0; nt < 4; nt++) {
                uint32_t addr = b_base + (nt * 8 * RS + ks * 16) * 2;
                ldm_x2(bh[nt], addr);
                ldm_x2(bl[nt], addr + SEG * 2);
            }
#pragma unroll
            for (int mt = 0; mt < 4; mt++)
#pragma unroll
                for (int nt = 0; nt < 4; nt++) {
                    mma_bf16(acc[mt][nt], ah[mt], bh[nt]);
                    mma_bf16(acc[mt][nt], ah[mt], bl[nt]);
                    mma_bf16(acc[mt][nt], al[mt], bh[nt]);
                }
        }
        __syncthreads();
        if (c + 1 < nchunks) {
            sstore(stage ^ 1);
            __syncthreads();
        }
    }

    const int r0 = bm + wm + (lane >> 2);
    const int c0 = bn + wn + (lane & 3) * 2;
    if (C) {
#pragma unroll
        for (int mt = 0; mt < 4; mt++)
#pragma unroll
            for (int nt = 0; nt < 4; nt++) {
                float* d0 = C + (size_t)(r0 + mt * 16) * N + c0 + nt * 8;
                float* d1 = d0 + 8 * N;
                *(float2*)d0 = make_float2(acc[mt][nt][0], acc[mt][nt][1]);
                *(float2*)d1 = make_float2(acc[mt][nt][2], acc[mt][nt][3]);
            }
    } else {
#pragma unroll
        for (int mt = 0; mt < 4; mt++)
#pragma unroll
            for (int nt = 0; nt < 4; nt++) {
                float v0 = acc[mt][nt][0] * scale;
                float v1 = acc[mt][nt][1] * scale;
                float v2 = acc[mt][nt][2] * scale;
                float v3 = acc[mt][nt][3] * scale;
                uint32_t h01 = pack_bf16x2(v0, v1);
                uint32_t l01 = pack_lo(v0, v1, h01);
                uint32_t h23 = pack_bf16x2(v2, v3);
                uint32_t l23 = pack_lo(v2, v3, h23);
                size_t o0 = (size_t)(r0 + mt * 16) * N + c0 + nt * 8;
                size_t o1 = o0 + (size_t)8 * N;
                *(uint32_t*)(Chi + o0) = h01;
                *(uint32_t*)(Clo + o0) = l01;
                *(uint32_t*)(Chi + o1) = h23;
                *(uint32_t*)(Clo + o1) = l23;
            }
    }
}

// ===========================================================================
// Tensor-core causal flash attention, split-KV warp pairs.
// CTA = 128 q rows x 1 head; 512 threads = 16 warps = 8 row-groups x 2 halves.
// Warp (g, hf) handles rows [g*16, g*16+16) and keys [hf*32, hf*32+32) of
// each 64-key tile, with its own online-softmax stats; pairs merge at the end.
// smem rows (RS2=72 bf16 each):
//   [0..127] Qhi  [128..255] Qlo
//   stage s at 256+s*256:  Khi(64) Klo(64) Vhi(64) Vlo(64)
// ===========================================================================
#define RS2 72
#define ATTN_SMEM (768 * RS2 * 2)   // 110592 bytes
#define MRG_STRIDE 68               // merge buffer row stride (floats)
#define MRG_GRP (16 * MRG_STRIDE + 32)

__global__ __launch_bounds__(512, 1)
void attn_mma(const __nv_bfloat16* __restrict__ Qh,
              const __nv_bfloat16* __restrict__ Ql,
              const __nv_bfloat16* __restrict__ Kh,
              const __nv_bfloat16* __restrict__ Kl,
              const __nv_bfloat16* __restrict__ Vh,
              const __nv_bfloat16* __restrict__ Vl,
              float* __restrict__ Z) {
    extern __shared__ __nv_bfloat16 sm[];
    const uint32_t sb = smem_u32(sm);
    const int qb   = (int)gridDim.x - 1 - (int)blockIdx.x;  // big tiles first
    const int h    = blockIdx.y;
    const int t    = threadIdx.x;
    const int lane = t & 31;
    const int w    = t >> 5;
    const int g    = w >> 1;      // row group 0..7
    const int hf   = w & 1;       // key half 0/1

    auto issue_kv = [&](int kb, int s) {
        const __nv_bfloat16* bases[4] = {Kh, Kl, Vh, Vl};
#pragma unroll
        for (int i = 0; i < 4; i++) {
            int idx = t + i * 512;
            int mtx = idx >> 9;
            int r   = (idx >> 3) & 63;
            int c8  = (idx & 7) * 8;
            const __nv_bfloat16* src =
                bases[mtx] + (size_t)(kb * 64 + r) * DIM + h * 64 + c8;
            uint32_t dst =
                sb + ((256 + s * 256 + mtx * 64 + r) * RS2 + c8) * 2;
            CP_ASYNC16(dst, src);
        }
    };

    // ---- prologue: Q (hi+lo) + stage 0 K/V ----
    {
#pragma unroll
        for (int i = 0; i < 4; i++) {
            int idx = t + i * 512;
            int buf = idx >> 10;
            int r   = (idx >> 3) & 127;
            int c8  = (idx & 7) * 8;
            const __nv_bfloat16* src =
                (buf ? Ql : Qh) + (size_t)(qb * 128 + r) * DIM + h * 64 + c8;
            uint32_t dst = sb + ((buf * 128 + r) * RS2 + c8) * 2;
            CP_ASYNC16(dst, src);
        }
        issue_kv(0, 0);
        CP_COMMIT();
        CP_WAIT0();
    }
    __syncthreads();

    const uint32_t q_base =
        sb + ((g * 16 + (lane & 15)) * RS2 + (lane >> 4) * 8) * 2;

    float o[8][4] = {};
    float m0 = -1e30f, m1 = -1e30f, l0 = 0.f, l1 = 0.f;
    const int row0 = qb * 128 + g * 16 + (lane >> 2);

    const int nkb = 2 * qb + 2;
    for (int kb = 0; kb < nkb; kb++) {
        const int s = kb & 1;
        if (kb + 1 < nkb) { issue_kv(kb + 1, s ^ 1); CP_COMMIT(); }

        // warp's first key <= warp's max row?
        const bool active = (kb * 64 + hf * 32 <= qb * 128 + g * 16 + 15);
        if (active) {
            const int KB = 256 + s * 256;        // Khi rows
            const int VB = KB + 128;             // Vhi rows

            // ---- S = Q K^T on this warp's 32 keys (3-pass split) ----
            float c[4][4] = {};
#pragma unroll
            for (int ks = 0; ks < 4; ks++) {
                uint32_t qhf[4], qlf[4];
                ldm_x4(qhf, q_base + ks * 32);
                ldm_x4(qlf, q_base + ks * 32 + 128 * RS2 * 2);
#pragma unroll
                for (int ntp = 0; ntp < 2; ntp++) {
                    uint32_t fh[4], fl[4];
                    uint32_t addr = sb +
                        ((KB + hf * 32 + ntp * 16 + (lane & 15)) * RS2 +
                         ks * 16 + (lane >> 4) * 8) * 2;
                    ldm_x4(fh, addr);
                    ldm_x4(fl, addr + 64 * RS2 * 2);
                    uint32_t beh[2] = {fh[0], fh[2]}, bel[2] = {fl[0], fl[2]};
                    uint32_t boh[2] = {fh[1], fh[3]}, bol[2] = {fl[1], fl[3]};
                    mma_bf16(c[2 * ntp],     qhf, beh);
                    mma_bf16(c[2 * ntp],     qhf, bel);
                    mma_bf16(c[2 * ntp],     qlf, beh);
                    mma_bf16(c[2 * ntp + 1], qhf, boh);
                    mma_bf16(c[2 * ntp + 1], qhf, bol);
                    mma_bf16(c[2 * ntp + 1], qlf, boh);
                }
            }

            // ---- causal mask ----
            if (kb * 64 + hf * 32 + 31 > row0) {
                const int colbase = kb * 64 + hf * 32 + (lane & 3) * 2;
#pragma unroll
                for (int nt = 0; nt < 4; nt++) {
                    int cc = colbase + nt * 8;
                    if (cc     > row0)     c[nt][0] = -1e30f;
                    if (cc + 1 > row0)     c[nt][1] = -1e30f;
                    if (cc     > row0 + 8) c[nt][2] = -1e30f;
                    if (cc + 1 > row0 + 8) c[nt][3] = -1e30f;
                }
            }

            // ---- online softmax (this warp's keys only) ----
            float mx0 = -1e30f, mx1 = -1e30f;
#pragma unroll
            for (int nt = 0; nt < 4; nt++) {
                mx0 = fmaxf(mx0, fmaxf(c[nt][0], c[nt][1]));
                mx1 = fmaxf(mx1, fmaxf(c[nt][2], c[nt][3]));
            }
            mx0 = fmaxf(mx0, __shfl_xor_sync(0xffffffffu, mx0, 1));
            mx0 = fmaxf(mx0, __shfl_xor_sync(0xffffffffu, mx0, 2));
            mx1 = fmaxf(mx1, __shfl_xor_sync(0xffffffffu, mx1, 1));
            mx1 = fmaxf(mx1, __shfl_xor_sync(0xffffffffu, mx1, 2));
            float M0 = fmaxf(m0, mx0);
            float M1 = fmaxf(m1, mx1);
            float sc0 = __expf(m0 - M0);
            float sc1 = __expf(m1 - M1);
            m0 = M0; m1 = M1;
            float s0 = 0.f, s1 = 0.f;
#pragma unroll
            for (int nt = 0; nt < 4; nt++) {
                c[nt][0] = __expf(c[nt][0] - M0);
                c[nt][1] = __expf(c[nt][1] - M0);
                c[nt][2] = __expf(c[nt][2] - M1);
                c[nt][3] = __expf(c[nt][3] - M1);
                s0 += c[nt][0] + c[nt][1];
                s1 += c[nt][2] + c[nt][3];
            }
            s0 += __shfl_xor_sync(0xffffffffu, s0, 1);
            s0 += __shfl_xor_sync(0xffffffffu, s0, 2);
            s1 += __shfl_xor_sync(0xffffffffu, s1, 1);
            s1 += __shfl_xor_sync(0xffffffffu, s1, 2);
            l0 = l0 * sc0 + s0;
            l1 = l1 * sc1 + s1;
#pragma unroll
            for (int nt = 0; nt < 8; nt++) {
                o[nt][0] *= sc0; o[nt][1] *= sc0;
                o[nt][2] *= sc1; o[nt][3] *= sc1;
            }

            // ---- O += P V over this warp's 32 keys (3-pass split) ----
#pragma unroll
            for (int ks = 0; ks < 2; ks++) {
                uint32_t ah[4], al[4];
                ah[0] = pack_bf16x2(c[2 * ks][0],     c[2 * ks][1]);
                ah[1] = pack_bf16x2(c[2 * ks][2],     c[2 * ks][3]);
                ah[2] = pack_bf16x2(c[2 * ks + 1][0], c[2 * ks + 1][1]);
                ah[3] = pack_bf16x2(c[2 * ks + 1][2], c[2 * ks + 1][3]);
                al[0] = pack_lo(c[2 * ks][0],     c[2 * ks][1],     ah[0]);
                al[1] = pack_lo(c[2 * ks][2],     c[2 * ks][3],     ah[1]);
                al[2] = pack_lo(c[2 * ks + 1][0], c[2 * ks + 1][1], ah[2]);
                al[3] = pack_lo(c[2 * ks + 1][2], c[2 * ks + 1][3], ah[3]);
#pragma unroll
                for (int ntp = 0; ntp < 4; ntp++) {
                    uint32_t fh[4], fl[4];
                    uint32_t addr = sb +
                        ((VB + hf * 32 + ks * 16 + (lane & 15)) * RS2 +
                         ntp * 16 + (lane >> 4) * 8) * 2;
                    ldm_x4t(fh, addr);
                    ldm_x4t(fl, addr + 64 * RS2 * 2);
                    uint32_t veh[2] = {fh[0], fh[1]}, vel[2] = {fl[0], fl[1]};
                    uint32_t voh[2] = {fh[2], fh[3]}, vol[2] = {fl[2], fl[3]};
                    mma_bf16(o[2 * ntp],     ah, veh);
                    mma_bf16(o[2 * ntp],     ah, vel);
                    mma_bf16(o[2 * ntp],     al, veh);
                    mma_bf16(o[2 * ntp + 1], ah, voh);
                    mma_bf16(o[2 * ntp + 1], ah, vol);
                    mma_bf16(o[2 * ntp + 1], al, voh);
                }
            }
        }
        if (kb + 1 < nkb) CP_WAIT0();
        __syncthreads();
    }

    // ---- merge warp pairs via smem (hf=1 publishes, hf=0 merges+stores) ----
    float* smf = (float*)sm;
    const int r4 = lane >> 2;          // 0..7
    const int c2 = (lane & 3) * 2;
    if (hf == 1) {
        float* gbuf = smf + g * MRG_GRP;
#pragma unroll
        for (int nt = 0; nt < 8; nt++) {
            float* p0 = gbuf + r4 * MRG_STRIDE + c2 + nt * 8;
            p0[0] = o[nt][0];
            p0[1] = o[nt][1];
            float* p1 = gbuf + (r4 + 8) * MRG_STRIDE + c2 + nt * 8;
            p1[0] = o[nt][2];
            p1[1] = o[nt][3];
        }
        if ((lane & 3) == 0) {
            gbuf[16 * MRG_STRIDE + r4]      = m0;
            gbuf[16 * MRG_STRIDE + 8 + r4]  = m1;
            gbuf[16 * MRG_STRIDE + 16 + r4] = l0;
            gbuf[16 * MRG_STRIDE + 24 + r4] = l1;
        }
    }
    __syncthreads();
    if (hf == 0) {
        float* gbuf = smf + g * MRG_GRP;
        float mb0 = gbuf[16 * MRG_STRIDE + r4];
        float mb1 = gbuf[16 * MRG_STRIDE + 8 + r4];
        float lb0 = gbuf[16 * MRG_STRIDE + 16 + r4];
        float lb1 = gbuf[16 * MRG_STRIDE + 24 + r4];
        float M0 = fmaxf(m0, mb0);
        float M1 = fmaxf(m1, mb1);
        float ea0 = __expf(m0 - M0), eb0 = __expf(mb0 - M0);
        float ea1 = __expf(m1 - M1), eb1 = __expf(mb1 - M1);
        float inv0 = 1.0f / (l0 * ea0 + lb0 * eb0);
        float inv1 = 1.0f / (l1 * ea1 + lb1 * eb1);
        float* z0 = Z + (size_t)row0 * DIM + h * HD + c2;
#pragma unroll
        for (int nt = 0; nt < 8; nt++) {
            float* p0 = gbuf + r4 * MRG_STRIDE + c2 + nt * 8;
            float* p1 = gbuf + (r4 + 8) * MRG_STRIDE + c2 + nt * 8;
            *(float2*)(z0 + nt * 8) = make_float2(
                (o[nt][0] * ea0 + p0[0] * eb0) * inv0,
                (o[nt][1] * ea0 + p0[1] * eb0) * inv0);
            *(float2*)(z0 + (size_t)8 * DIM + nt * 8) = make_float2(
                (o[nt][2] * ea1 + p1[0] * eb1) * inv1,
                (o[nt][3] * ea1 + p1[1] * eb1) * inv1);
        }
    }
}

// ===========================================================================
extern "C" void kernel_launch(void* const* d_in, const int* in_sizes, int n_in,
                              void* d_out, int out_size) {
    const float* x  = (const float*)d_in[0];
    const float* Wq = (const float*)d_in[1];
    const float* Wk = (const float*)d_in[2];
    const float* Wv = (const float*)d_in[3];
    const float* Wo = (const float*)d_in[4];
    float* out = (float*)d_out;

    __nv_bfloat16 *dQh, *dQl, *dKh, *dKl, *dVh, *dVl;
    float* dZ;
    cudaGetSymbolAddress((void**)&dQh, g_Qh);
    cudaGetSymbolAddress((void**)&dQl, g_Ql);
    cudaGetSymbolAddress((void**)&dKh, g_Kh);
    cudaGetSymbolAddress((void**)&dKl, g_Kl);
    cudaGetSymbolAddress((void**)&dVh, g_Vh);
    cudaGetSymbolAddress((void**)&dVl, g_Vl);
    cudaGetSymbolAddress((void**)&dZ, g_Z);

    cudaFuncSetAttribute(gemm_mma128,
                         cudaFuncAttributeMaxDynamicSharedMemorySize, GEMM_SMEM);
    cudaFuncSetAttribute(attn_mma,
                         cudaFuncAttributeMaxDynamicSharedMemorySize, ATTN_SMEM);

    dim3 gproj(DIM / 128, S_LEN / 128);   // (8, 32)
    gemm_mma128<<<gproj, 256, GEMM_SMEM>>>(x, Wq, nullptr, dQh, dQl, 0.125f,
                                           S_LEN, DIM, DIM);
    gemm_mma128<<<gproj, 256, GEMM_SMEM>>>(x, Wk, nullptr, dKh, dKl, 1.0f,
                                           S_LEN, DIM, DIM);
    gemm_mma128<<<gproj, 256, GEMM_SMEM>>>(x, Wv, nullptr, dVh, dVl, 1.0f,
                                           S_LEN, DIM, DIM);

    attn_mma<<<dim3(S_LEN / 128, NH), 512, ATTN_SMEM>>>(dQh, dQl, dKh, dKl,
                                                        dVh, dVl, dZ);

    gemm_mma128<<<gproj, 256, GEMM_SMEM>>>(dZ, Wo, out, nullptr, nullptr, 1.0f,
                                           S_LEN, DIM, DIM);
}

// round 9
// speedup vs baseline: 1.1899x; 1.1441x over previous
#include <cuda_runtime.h>
#include <cuda_bf16.h>
#include <cuda_fp16.h>
#include <cstdint>

#define DIM 1024
#define S_LEN 4096
#define NH 16
#define HD 64

// Scratch (allocation-free rule: __device__ globals)
__device__ __nv_bfloat16 g_Qh[S_LEN * DIM];
__device__ __nv_bfloat16 g_Ql[S_LEN * DIM];
__device__ __nv_bfloat16 g_Kh[S_LEN * DIM];
__device__ __nv_bfloat16 g_Kl[S_LEN * DIM];
__device__ __half        g_V [S_LEN * DIM];
__device__ float g_Z[S_LEN * DIM];

#define QSCALE 0.18033688f   // 0.125 * log2(e): logits in log2 domain

// ===========================================================================
// Base-ISA tensor-core helpers (compute_103-safe: ldmatrix + mma.sync)
// ===========================================================================
__device__ __forceinline__ uint32_t smem_u32(const void* p) {
    uint32_t a;
    asm("{ .reg .u64 t; cvta.to.shared.u64 t, %1; cvt.u32.u64 %0, t; }"
        : "=r"(a) : "l"(p));
    return a;
}

__device__ __forceinline__ void ldm_x4(uint32_t* f, uint32_t addr) {
    asm volatile("ldmatrix.sync.aligned.m8n8.x4.shared.b16 {%0,%1,%2,%3}, [%4];"
                 : "=r"(f[0]), "=r"(f[1]), "=r"(f[2]), "=r"(f[3]) : "r"(addr));
}
__device__ __forceinline__ void ldm_x4t(uint32_t* f, uint32_t addr) {
    asm volatile("ldmatrix.sync.aligned.m8n8.x4.trans.shared.b16 {%0,%1,%2,%3}, [%4];"
                 : "=r"(f[0]), "=r"(f[1]), "=r"(f[2]), "=r"(f[3]) : "r"(addr));
}
__device__ __forceinline__ void ldm_x2(uint32_t* f, uint32_t addr) {
    asm volatile("ldmatrix.sync.aligned.m8n8.x2.shared.b16 {%0,%1}, [%2];"
                 : "=r"(f[0]), "=r"(f[1]) : "r"(addr));
}
__device__ __forceinline__ void mma_bf16(float* c, const uint32_t* a,
                                         const uint32_t* b) {
    asm volatile(
        "mma.sync.aligned.m16n8k16.row.col.f32.bf16.bf16.f32 "
        "{%0,%1,%2,%3}, {%4,%5,%6,%7}, {%8,%9}, {%0,%1,%2,%3};"
        : "+f"(c[0]), "+f"(c[1]), "+f"(c[2]), "+f"(c[3])
        : "r"(a[0]), "r"(a[1]), "r"(a[2]), "r"(a[3]), "r"(b[0]), "r"(b[1]));
}
__device__ __forceinline__ void mma_f16(float* c, const uint32_t* a,
                                        const uint32_t* b) {
    asm volatile(
        "mma.sync.aligned.m16n8k16.row.col.f32.f16.f16.f32 "
        "{%0,%1,%2,%3}, {%4,%5,%6,%7}, {%8,%9}, {%0,%1,%2,%3};"
        : "+f"(c[0]), "+f"(c[1]), "+f"(c[2]), "+f"(c[3])
        : "r"(a[0]), "r"(a[1]), "r"(a[2]), "r"(a[3]), "r"(b[0]), "r"(b[1]));
}

__device__ __forceinline__ uint32_t pack_bf16x2(float x, float y) {
    __nv_bfloat162 p;
    p.x = __float2bfloat16(x);
    p.y = __float2bfloat16(y);
    return *(uint32_t*)&p;
}
__device__ __forceinline__ uint32_t pack_lo(float x, float y, uint32_t hi) {
    __nv_bfloat162 h = *(__nv_bfloat162*)&hi;
    return pack_bf16x2(x - __bfloat162float(h.x), y - __bfloat162float(h.y));
}
__device__ __forceinline__ uint32_t pack_h2(float x, float y) {
    __half2 p;
    p.x = __float2half_rn(x);
    p.y = __float2half_rn(y);
    return *(uint32_t*)&p;
}
__device__ __forceinline__ uint32_t pack_h2_lo(float x, float y, uint32_t hi) {
    __half2 h = *(__half2*)&hi;
    return pack_h2(x - __half2float(h.x), y - __half2float(h.y));
}

#define CP_ASYNC16(dst, src)                                                   \
    asm volatile("cp.async.cg.shared.global [%0], [%1], 16;"                   \
                 :: "r"(dst), "l"(src))
#define CP_COMMIT() asm volatile("cp.async.commit_group;" ::: "memory")
#define CP_WAIT0()  asm volatile("cp.async.wait_group 0;" ::: "memory")

// ===========================================================================
// Tensor GEMM-NT:  C = A * B^T  (A,B fp32 row-major, K contiguous)
// MODE 0: bf16 3-pass,  out = bf16 hi/lo pair          (Q, K projections)
// MODE 1: fp16 2-pass (A split, B single), out = fp16  (V projection)
// MODE 2: fp16 2-pass (A split, B single), out = fp32  (output projection)
// ===========================================================================
#define RS 40
#define SEG (128 * RS)
#define STAGE_ELEMS (4 * SEG)
#define STAGE_BYTES (STAGE_ELEMS * 2)
#define GEMM_SMEM (2 * STAGE_BYTES)

template <int MODE>
__device__ __forceinline__
void gemm_body(const float* __restrict__ A, const float* __restrict__ B,
               float* __restrict__ C, __nv_bfloat16* __restrict__ Chi,
               __nv_bfloat16* __restrict__ Clo, __half* __restrict__ Ch,
               float scale, int M, int N, int Kd, __nv_bfloat16* smem) {
    const uint32_t sb = smem_u32(smem);
    const int t    = threadIdx.x;
    const int lane = t & 31;
    const int wid  = t >> 5;
    const int wm   = (wid >> 2) * 64;
    const int wn   = (wid & 3) * 32;
    const int bm   = blockIdx.y * 128;
    const int bn   = blockIdx.x * 128;

    float acc[4][4][4] = {};
    float4 pa[4], pb[4];

    auto gload = [&](int k0) {
#pragma unroll
        for (int i = 0; i < 4; i++) {
            int id  = t + i * 256;
            int row = id >> 3;
            int col = (id & 7) * 4;
            pa[i] = *(const float4*)(A + (size_t)(bm + row) * Kd + k0 + col);
            pb[i] = *(const float4*)(B + (size_t)(bn + row) * Kd + k0 + col);
        }
    };

    auto sstore = [&](int stage) {
        __nv_bfloat16* base = smem + stage * STAGE_ELEMS;
#pragma unroll
        for (int i = 0; i < 4; i++) {
            int id  = t + i * 256;
            int row = id >> 3;
            int col = (id & 7) * 4;
            int off = row * RS + col;
            float4 va = pa[i];
            float4 vb = pb[i];
            if (MODE == 0) {
                uint32_t ah0 = pack_bf16x2(va.x, va.y);
                uint32_t ah1 = pack_bf16x2(va.z, va.w);
                uint32_t al0 = pack_lo(va.x, va.y, ah0);
                uint32_t al1 = pack_lo(va.z, va.w, ah1);
                uint32_t bh0 = pack_bf16x2(vb.x, vb.y);
                uint32_t bh1 = pack_bf16x2(vb.z, vb.w);
                uint32_t bl0 = pack_lo(vb.x, vb.y, bh0);
                uint32_t bl1 = pack_lo(vb.z, vb.w, bh1);
                *(uint2*)(base + 0 * SEG + off) = make_uint2(ah0, ah1);
                *(uint2*)(base + 1 * SEG + off) = make_uint2(al0, al1);
                *(uint2*)(base + 2 * SEG + off) = make_uint2(bh0, bh1);
                *(uint2*)(base + 3 * SEG + off) = make_uint2(bl0, bl1);
            } else {
                uint32_t ah0 = pack_h2(va.x, va.y);
                uint32_t ah1 = pack_h2(va.z, va.w);
                uint32_t al0 = pack_h2_lo(va.x, va.y, ah0);
                uint32_t al1 = pack_h2_lo(va.z, va.w, ah1);
                uint32_t bh0 = pack_h2(vb.x, vb.y);
                uint32_t bh1 = pack_h2(vb.z, vb.w);
                *(uint2*)(base + 0 * SEG + off) = make_uint2(ah0, ah1);
                *(uint2*)(base + 1 * SEG + off) = make_uint2(al0, al1);
                *(uint2*)(base + 2 * SEG + off) = make_uint2(bh0, bh1);
            }
        }
    };

    const int nchunks = Kd / 32;
    gload(0);
    sstore(0);
    __syncthreads();

    for (int c = 0; c < nchunks; c++) {
        const int stage = c & 1;
        if (c + 1 < nchunks) gload((c + 1) * 32);

        const uint32_t sstage = sb + stage * STAGE_BYTES;
        const uint32_t a_base =
            sstage + ((wm + (lane & 15)) * RS + (lane >> 4) * 8) * 2;
        const uint32_t b_base =
            sstage + 2 * SEG * 2 +
            ((wn + (lane & 7)) * RS + (((lane & 15) >> 3) * 8)) * 2;

#pragma unroll
        for (int ks = 0; ks < 2; ks++) {
            uint32_t ah[4][4], al[4][4], bh[4][2], bl[4][2];
#pragma unroll
            for (int mt = 0; mt < 4; mt++) {
                uint32_t addr = a_base + (mt * 16 * RS + ks * 16) * 2;
                ldm_x4(ah[mt], addr);
                ldm_x4(al[mt], addr + SEG * 2);
            }
#pragma unroll
            for (int nt = 0; nt < 4; nt++) {
                uint32_t addr = b_base + (nt * 8 * RS + ks * 16) * 2;
                ldm_x2(bh[nt], addr);
                if (MODE == 0) ldm_x2(bl[nt], addr + SEG * 2);
            }
#pragma unroll
            for (int mt = 0; mt < 4; mt++)
#pragma unroll
                for (int nt = 0; nt < 4; nt++) {
                    if (MODE == 0) {
                        mma_bf16(acc[mt][nt], ah[mt], bh[nt]);
                        mma_bf16(acc[mt][nt], ah[mt], bl[nt]);
                        mma_bf16(acc[mt][nt], al[mt], bh[nt]);
                    } else {
                        mma_f16(acc[mt][nt], ah[mt], bh[nt]);
                        mma_f16(acc[mt][nt], al[mt], bh[nt]);
                    }
                }
        }
        __syncthreads();
        if (c + 1 < nchunks) {
            sstore(stage ^ 1);
            __syncthreads();
        }
    }

    const int r0 = bm + wm + (lane >> 2);
    const int c0 = bn + wn + (lane & 3) * 2;
#pragma unroll
    for (int mt = 0; mt < 4; mt++)
#pragma unroll
        for (int nt = 0; nt < 4; nt++) {
            size_t o0 = (size_t)(r0 + mt * 16) * N + c0 + nt * 8;
            size_t o1 = o0 + (size_t)8 * N;
            if (MODE == 2) {
                *(float2*)(C + o0) = make_float2(acc[mt][nt][0], acc[mt][nt][1]);
                *(float2*)(C + o1) = make_float2(acc[mt][nt][2], acc[mt][nt][3]);
            } else if (MODE == 1) {
                *(uint32_t*)(Ch + o0) = pack_h2(acc[mt][nt][0], acc[mt][nt][1]);
                *(uint32_t*)(Ch + o1) = pack_h2(acc[mt][nt][2], acc[mt][nt][3]);
            } else {
                float v0 = acc[mt][nt][0] * scale;
                float v1 = acc[mt][nt][1] * scale;
                float v2 = acc[mt][nt][2] * scale;
                float v3 = acc[mt][nt][3] * scale;
                uint32_t h01 = pack_bf16x2(v0, v1);
                uint32_t h23 = pack_bf16x2(v2, v3);
                *(uint32_t*)(Chi + o0) = h01;
                *(uint32_t*)(Clo + o0) = pack_lo(v0, v1, h01);
                *(uint32_t*)(Chi + o1) = h23;
                *(uint32_t*)(Clo + o1) = pack_lo(v2, v3, h23);
            }
        }
}

__global__ __launch_bounds__(256, 1)
void gemm_qk(const float* __restrict__ A, const float* __restrict__ B,
             __nv_bfloat16* __restrict__ Chi, __nv_bfloat16* __restrict__ Clo,
             float scale) {
    extern __shared__ __nv_bfloat16 smem[];
    gemm_body<0>(A, B, nullptr, Chi, Clo, nullptr, scale, S_LEN, DIM, DIM, smem);
}
__global__ __launch_bounds__(256, 1)
void gemm_v(const float* __restrict__ A, const float* __restrict__ B,
            __half* __restrict__ Ch) {
    extern __shared__ __nv_bfloat16 smem[];
    gemm_body<1>(A, B, nullptr, nullptr, nullptr, Ch, 1.0f, S_LEN, DIM, DIM, smem);
}
__global__ __launch_bounds__(256, 1)
void gemm_out(const float* __restrict__ A, const float* __restrict__ B,
              float* __restrict__ C) {
    extern __shared__ __nv_bfloat16 smem[];
    gemm_body<2>(A, B, C, nullptr, nullptr, nullptr, 1.0f, S_LEN, DIM, DIM, smem);
}

// ===========================================================================
// Tensor-core causal flash attention, split-KV warp pairs.
// QK: bf16 3-pass (Q hi/lo x K hi/lo).  PV: fp16 2-pass (P hi/lo x V single).
// Logits in log2 domain (log2e folded into Q scale) -> exp2f softmax.
// CTA = 128 q rows x 1 head; 512 threads = 8 row-groups x 2 key-halves.
// smem rows (RS2=72 bf16 each):
//   [0..127] Qhi  [128..255] Qlo
//   stage s at 256+s*192:  Khi(64) Klo(64) V-fp16(64)
// ===========================================================================
#define RS2 72
#define ATTN_SMEM (640 * RS2 * 2)   // 92160 bytes
#define MRG_STRIDE 68
#define MRG_GRP (16 * MRG_STRIDE + 32)

__global__ __launch_bounds__(512, 1)
void attn_mma(const __nv_bfloat16* __restrict__ Qh,
              const __nv_bfloat16* __restrict__ Ql,
              const __nv_bfloat16* __restrict__ Kh,
              const __nv_bfloat16* __restrict__ Kl,
              const __half* __restrict__ V,
              float* __restrict__ Z) {
    extern __shared__ __nv_bfloat16 sm[];
    const uint32_t sb = smem_u32(sm);
    const int qb   = (int)gridDim.x - 1 - (int)blockIdx.x;  // big tiles first
    const int h    = blockIdx.y;
    const int t    = threadIdx.x;
    const int lane = t & 31;
    const int w    = t >> 5;
    const int g    = w >> 1;      // row group 0..7
    const int hf   = w & 1;       // key half 0/1

    auto issue_kv = [&](int kb, int s) {
#pragma unroll
        for (int i = 0; i < 3; i++) {
            int idx = t + i * 512;
            int mtx = idx >> 9;           // 0=Kh 1=Kl 2=V
            int r   = (idx >> 3) & 63;
            int c8  = (idx & 7) * 8;
            const char* src =
                (mtx == 0) ? (const char*)(Kh + (size_t)(kb * 64 + r) * DIM + h * 64 + c8)
              : (mtx == 1) ? (const char*)(Kl + (size_t)(kb * 64 + r) * DIM + h * 64 + c8)
                           : (const char*)(V  + (size_t)(kb * 64 + r) * DIM + h * 64 + c8);
            uint32_t dst =
                sb + ((256 + s * 192 + mtx * 64 + r) * RS2 + c8) * 2;
            CP_ASYNC16(dst, src);
        }
    };

    // ---- prologue: Q (hi+lo) + stage 0 K/V ----
    {
#pragma unroll
        for (int i = 0; i < 4; i++) {
            int idx = t + i * 512;
            int buf = idx >> 10;
            int r   = (idx >> 3) & 127;
            int c8  = (idx & 7) * 8;
            const __nv_bfloat16* src =
                (buf ? Ql : Qh) + (size_t)(qb * 128 + r) * DIM + h * 64 + c8;
            uint32_t dst = sb + ((buf * 128 + r) * RS2 + c8) * 2;
            CP_ASYNC16(dst, src);
        }
        issue_kv(0, 0);
        CP_COMMIT();
        CP_WAIT0();
    }
    __syncthreads();

    const uint32_t q_base =
        sb + ((g * 16 + (lane & 15)) * RS2 + (lane >> 4) * 8) * 2;

    float o[8][4] = {};
    float m0 = -1e30f, m1 = -1e30f, l0 = 0.f, l1 = 0.f;
    const int row0 = qb * 128 + g * 16 + (lane >> 2);

    const int nkb = 2 * qb + 2;
    for (int kb = 0; kb < nkb; kb++) {
        const int s = kb & 1;
        if (kb + 1 < nkb) { issue_kv(kb + 1, s ^ 1); CP_COMMIT(); }

        const bool active = (kb * 64 + hf * 32 <= qb * 128 + g * 16 + 15);
        if (active) {
            const int KB = 256 + s * 192;        // Khi rows
            const int VB = KB + 128;             // V rows

            // ---- S = Q K^T on this warp's 32 keys (bf16 3-pass) ----
            float c[4][4] = {};
#pragma unroll
            for (int ks = 0; ks < 4; ks++) {
                uint32_t qhf[4], qlf[4];
                ldm_x4(qhf, q_base + ks * 32);
                ldm_x4(qlf, q_base + ks * 32 + 128 * RS2 * 2);
#pragma unroll
                for (int ntp = 0; ntp < 2; ntp++) {
                    uint32_t fh[4], fl[4];
                    uint32_t addr = sb +
                        ((KB + hf * 32 + ntp * 16 + (lane & 15)) * RS2 +
                         ks * 16 + (lane >> 4) * 8) * 2;
                    ldm_x4(fh, addr);
                    ldm_x4(fl, addr + 64 * RS2 * 2);
                    uint32_t beh[2] = {fh[0], fh[2]}, bel[2] = {fl[0], fl[2]};
                    uint32_t boh[2] = {fh[1], fh[3]}, bol[2] = {fl[1], fl[3]};
                    mma_bf16(c[2 * ntp],     qhf, beh);
                    mma_bf16(c[2 * ntp],     qhf, bel);
                    mma_bf16(c[2 * ntp],     qlf, beh);
                    mma_bf16(c[2 * ntp + 1], qhf, boh);
                    mma_bf16(c[2 * ntp + 1], qhf, bol);
                    mma_bf16(c[2 * ntp + 1], qlf, boh);
                }
            }

            // ---- causal mask ----
            if (kb * 64 + hf * 32 + 31 > row0) {
                const int colbase = kb * 64 + hf * 32 + (lane & 3) * 2;
#pragma unroll
                for (int nt = 0; nt < 4; nt++) {
                    int cc = colbase + nt * 8;
                    if (cc     > row0)     c[nt][0] = -1e30f;
                    if (cc + 1 > row0)     c[nt][1] = -1e30f;
                    if (cc     > row0 + 8) c[nt][2] = -1e30f;
                    if (cc + 1 > row0 + 8) c[nt][3] = -1e30f;
                }
            }

            // ---- online softmax (log2 domain) ----
            float mx0 = -1e30f, mx1 = -1e30f;
#pragma unroll
            for (int nt = 0; nt < 4; nt++) {
                mx0 = fmaxf(mx0, fmaxf(c[nt][0], c[nt][1]));
                mx1 = fmaxf(mx1, fmaxf(c[nt][2], c[nt][3]));
            }
            mx0 = fmaxf(mx0, __shfl_xor_sync(0xffffffffu, mx0, 1));
            mx0 = fmaxf(mx0, __shfl_xor_sync(0xffffffffu, mx0, 2));
            mx1 = fmaxf(mx1, __shfl_xor_sync(0xffffffffu, mx1, 1));
            mx1 = fmaxf(mx1, __shfl_xor_sync(0xffffffffu, mx1, 2));
            float M0 = fmaxf(m0, mx0);
            float M1 = fmaxf(m1, mx1);
            float sc0 = exp2f(m0 - M0);
            float sc1 = exp2f(m1 - M1);
            m0 = M0; m1 = M1;
            float s0 = 0.f, s1 = 0.f;
#pragma unroll
            for (int nt = 0; nt < 4; nt++) {
                c[nt][0] = exp2f(c[nt][0] - M0);
                c[nt][1] = exp2f(c[nt][1] - M0);
                c[nt][2] = exp2f(c[nt][2] - M1);
                c[nt][3] = exp2f(c[nt][3] - M1);
                s0 += c[nt][0] + c[nt][1];
                s1 += c[nt][2] + c[nt][3];
            }
            s0 += __shfl_xor_sync(0xffffffffu, s0, 1);
            s0 += __shfl_xor_sync(0xffffffffu, s0, 2);
            s1 += __shfl_xor_sync(0xffffffffu, s1, 1);
            s1 += __shfl_xor_sync(0xffffffffu, s1, 2);
            l0 = l0 * sc0 + s0;
            l1 = l1 * sc1 + s1;
#pragma unroll
            for (int nt = 0; nt < 8; nt++) {
                o[nt][0] *= sc0; o[nt][1] *= sc0;
                o[nt][2] *= sc1; o[nt][3] *= sc1;
            }

            // ---- O += P V (fp16 2-pass: P hi/lo, V single) ----
#pragma unroll
            for (int ks = 0; ks < 2; ks++) {
                uint32_t ph[4], pl[4];
                ph[0] = pack_h2(c[2 * ks][0],     c[2 * ks][1]);
                ph[1] = pack_h2(c[2 * ks][2],     c[2 * ks][3]);
                ph[2] = pack_h2(c[2 * ks + 1][0], c[2 * ks + 1][1]);
                ph[3] = pack_h2(c[2 * ks + 1][2], c[2 * ks + 1][3]);
                pl[0] = pack_h2_lo(c[2 * ks][0],     c[2 * ks][1],     ph[0]);
                pl[1] = pack_h2_lo(c[2 * ks][2],     c[2 * ks][3],     ph[1]);
                pl[2] = pack_h2_lo(c[2 * ks + 1][0], c[2 * ks + 1][1], ph[2]);
                pl[3] = pack_h2_lo(c[2 * ks + 1][2], c[2 * ks + 1][3], ph[3]);
#pragma unroll
                for (int ntp = 0; ntp < 4; ntp++) {
                    uint32_t fh[4];
                    uint32_t addr = sb +
                        ((VB + hf * 32 + ks * 16 + (lane & 15)) * RS2 +
                         ntp * 16 + (lane >> 4) * 8) * 2;
                    ldm_x4t(fh, addr);
                    uint32_t veh[2] = {fh[0], fh[1]};
                    uint32_t voh[2] = {fh[2], fh[3]};
                    mma_f16(o[2 * ntp],     ph, veh);
                    mma_f16(o[2 * ntp],     pl, veh);
                    mma_f16(o[2 * ntp + 1], ph, voh);
                    mma_f16(o[2 * ntp + 1], pl, voh);
                }
            }
        }
        if (kb + 1 < nkb) CP_WAIT0();
        __syncthreads();
    }

    // ---- merge warp pairs via smem (hf=1 publishes, hf=0 merges+stores) ----
    float* smf = (float*)sm;
    const int r4 = lane >> 2;
    const int c2 = (lane & 3) * 2;
    if (hf == 1) {
        float* gbuf = smf + g * MRG_GRP;
#pragma unroll
        for (int nt = 0; nt < 8; nt++) {
            float* p0 = gbuf + r4 * MRG_STRIDE + c2 + nt * 8;
            p0[0] = o[nt][0];
            p0[1] = o[nt][1];
            float* p1 = gbuf + (r4 + 8) * MRG_STRIDE + c2 + nt * 8;
            p1[0] = o[nt][2];
            p1[1] = o[nt][3];
        }
        if ((lane & 3) == 0) {
            gbuf[16 * MRG_STRIDE + r4]      = m0;
            gbuf[16 * MRG_STRIDE + 8 + r4]  = m1;
            gbuf[16 * MRG_STRIDE + 16 + r4] = l0;
            gbuf[16 * MRG_STRIDE + 24 + r4] = l1;
        }
    }
    __syncthreads();
    if (hf == 0) {
        float* gbuf = smf + g * MRG_GRP;
        float mb0 = gbuf[16 * MRG_STRIDE + r4];
        float mb1 = gbuf[16 * MRG_STRIDE + 8 + r4];
        float lb0 = gbuf[16 * MRG_STRIDE + 16 + r4];
        float lb1 = gbuf[16 * MRG_STRIDE + 24 + r4];
        float M0 = fmaxf(m0, mb0);
        float M1 = fmaxf(m1, mb1);
        float ea0 = exp2f(m0 - M0), eb0 = exp2f(mb0 - M0);
        float ea1 = exp2f(m1 - M1), eb1 = exp2f(mb1 - M1);
        float inv0 = 1.0f / (l0 * ea0 + lb0 * eb0);
        float inv1 = 1.0f / (l1 * ea1 + lb1 * eb1);
        float* z0 = Z + (size_t)row0 * DIM + h * HD + c2;
#pragma unroll
        for (int nt = 0; nt < 8; nt++) {
            float* p0 = gbuf + r4 * MRG_STRIDE + c2 + nt * 8;
            float* p1 = gbuf + (r4 + 8) * MRG_STRIDE + c2 + nt * 8;
            *(float2*)(z0 + nt * 8) = make_float2(
                (o[nt][0] * ea0 + p0[0] * eb0) * inv0,
                (o[nt][1] * ea0 + p0[1] * eb0) * inv0);
            *(float2*)(z0 + (size_t)8 * DIM + nt * 8) = make_float2(
                (o[nt][2] * ea1 + p1[0] * eb1) * inv1,
                (o[nt][3] * ea1 + p1[1] * eb1) * inv1);
        }
    }
}

// ===========================================================================
extern "C" void kernel_launch(void* const* d_in, const int* in_sizes, int n_in,
                              void* d_out, int out_size) {
    const float* x  = (const float*)d_in[0];
    const float* Wq = (const float*)d_in[1];
    const float* Wk = (const float*)d_in[2];
    const float* Wv = (const float*)d_in[3];
    const float* Wo = (const float*)d_in[4];
    float* out = (float*)d_out;

    __nv_bfloat16 *dQh, *dQl, *dKh, *dKl;
    __half* dV;
    float* dZ;
    cudaGetSymbolAddress((void**)&dQh, g_Qh);
    cudaGetSymbolAddress((void**)&dQl, g_Ql);
    cudaGetSymbolAddress((void**)&dKh, g_Kh);
    cudaGetSymbolAddress((void**)&dKl, g_Kl);
    cudaGetSymbolAddress((void**)&dV, g_V);
    cudaGetSymbolAddress((void**)&dZ, g_Z);

    cudaFuncSetAttribute(gemm_qk,
                         cudaFuncAttributeMaxDynamicSharedMemorySize, GEMM_SMEM);
    cudaFuncSetAttribute(gemm_v,
                         cudaFuncAttributeMaxDynamicSharedMemorySize, GEMM_SMEM);
    cudaFuncSetAttribute(gemm_out,
                         cudaFuncAttributeMaxDynamicSharedMemorySize, GEMM_SMEM);
    cudaFuncSetAttribute(attn_mma,
                         cudaFuncAttributeMaxDynamicSharedMemorySize, ATTN_SMEM);

    dim3 gproj(DIM / 128, S_LEN / 128);   // (8, 32)
    gemm_qk<<<gproj, 256, GEMM_SMEM>>>(x, Wq, dQh, dQl, QSCALE);
    gemm_qk<<<gproj, 256, GEMM_SMEM>>>(x, Wk, dKh, dKl, 1.0f);
    gemm_v<<<gproj, 256, GEMM_SMEM>>>(x, Wv, dV);

    attn_mma<<<dim3(S_LEN / 128, NH), 512, ATTN_SMEM>>>(dQh, dQl, dKh, dKl,
                                                        dV, dZ);

    gemm_out<<<gproj, 256, GEMM_SMEM>>>(dZ, Wo, out);
}

// round 10
// speedup vs baseline: 1.4286x; 1.2006x over previous
#include <cuda_runtime.h>
#include <cuda_bf16.h>
#include <cuda_fp16.h>
#include <cstdint>

#define DIM 1024
#define S_LEN 4096
#define NH 16
#define HD 64

// Scratch (allocation-free rule: __device__ globals)
__device__ __half g_Qh[S_LEN * DIM];
__device__ __half g_Ql[S_LEN * DIM];
__device__ __half g_K [S_LEN * DIM];
__device__ __half g_V [S_LEN * DIM];
__device__ float  g_Z [S_LEN * DIM];

#define QSCALE 0.18033688f   // 0.125 * log2(e): logits in log2 domain

// ===========================================================================
// Base-ISA tensor-core helpers (compute_103-safe: ldmatrix + mma.sync)
// ===========================================================================
__device__ __forceinline__ uint32_t smem_u32(const void* p) {
    uint32_t a;
    asm("{ .reg .u64 t; cvta.to.shared.u64 t, %1; cvt.u32.u64 %0, t; }"
        : "=r"(a) : "l"(p));
    return a;
}

__device__ __forceinline__ void ldm_x4(uint32_t* f, uint32_t addr) {
    asm volatile("ldmatrix.sync.aligned.m8n8.x4.shared.b16 {%0,%1,%2,%3}, [%4];"
                 : "=r"(f[0]), "=r"(f[1]), "=r"(f[2]), "=r"(f[3]) : "r"(addr));
}
__device__ __forceinline__ void ldm_x4t(uint32_t* f, uint32_t addr) {
    asm volatile("ldmatrix.sync.aligned.m8n8.x4.trans.shared.b16 {%0,%1,%2,%3}, [%4];"
                 : "=r"(f[0]), "=r"(f[1]), "=r"(f[2]), "=r"(f[3]) : "r"(addr));
}
__device__ __forceinline__ void ldm_x2(uint32_t* f, uint32_t addr) {
    asm volatile("ldmatrix.sync.aligned.m8n8.x2.shared.b16 {%0,%1}, [%2];"
                 : "=r"(f[0]), "=r"(f[1]) : "r"(addr));
}
__device__ __forceinline__ void mma_f16(float* c, const uint32_t* a,
                                        const uint32_t* b) {
    asm volatile(
        "mma.sync.aligned.m16n8k16.row.col.f32.f16.f16.f32 "
        "{%0,%1,%2,%3}, {%4,%5,%6,%7}, {%8,%9}, {%0,%1,%2,%3};"
        : "+f"(c[0]), "+f"(c[1]), "+f"(c[2]), "+f"(c[3])
        : "r"(a[0]), "r"(a[1]), "r"(a[2]), "r"(a[3]), "r"(b[0]), "r"(b[1]));
}

__device__ __forceinline__ uint32_t pack_h2(float x, float y) {
    __half2 p;
    p.x = __float2half_rn(x);
    p.y = __float2half_rn(y);
    return *(uint32_t*)&p;
}
__device__ __forceinline__ uint32_t pack_h2_lo(float x, float y, uint32_t hi) {
    __half2 h = *(__half2*)&hi;
    return pack_h2(x - __half2float(h.x), y - __half2float(h.y));
}

#define CP_ASYNC16(dst, src)                                                   \
    asm volatile("cp.async.cg.shared.global [%0], [%1], 16;"                   \
                 :: "r"(dst), "l"(src))
#define CP_COMMIT() asm volatile("cp.async.commit_group;" ::: "memory")
#define CP_WAIT0()  asm volatile("cp.async.wait_group 0;" ::: "memory")

// ===========================================================================
// fp16 2-pass tensor GEMM-NT:  C = A * B^T  (A,B fp32 row-major, K contig)
// A split fp16 hi/lo (near-fp32), B single fp16.
// MODE 1: out single fp16        (K, V projections)
// MODE 2: out fp32               (output projection)
// MODE 3: out fp16 hi/lo, scaled (Q projection)
// ===========================================================================
#define RS 40
#define SEG (128 * RS)
#define STAGE_ELEMS (3 * SEG)             // Ahi | Alo | B
#define STAGE_BYTES (STAGE_ELEMS * 2)
#define GEMM_SMEM (2 * STAGE_BYTES)       // 61440

template <int MODE>
__device__ __forceinline__
void gemm_body(const float* __restrict__ A, const float* __restrict__ B,
               float* __restrict__ C, __half* __restrict__ Ch,
               __half* __restrict__ Chl, float scale,
               int M, int N, int Kd, __half* smem) {
    const uint32_t sb = smem_u32(smem);
    const int t    = threadIdx.x;
    const int lane = t & 31;
    const int wid  = t >> 5;
    const int wm   = (wid >> 2) * 64;
    const int wn   = (wid & 3) * 32;
    const int bm   = blockIdx.y * 128;
    const int bn   = blockIdx.x * 128;

    float acc[4][4][4] = {};
    float4 pa[4], pb[4];

    auto gload = [&](int k0) {
#pragma unroll
        for (int i = 0; i < 4; i++) {
            int id  = t + i * 256;
            int row = id >> 3;
            int col = (id & 7) * 4;
            pa[i] = *(const float4*)(A + (size_t)(bm + row) * Kd + k0 + col);
            pb[i] = *(const float4*)(B + (size_t)(bn + row) * Kd + k0 + col);
        }
    };

    auto sstore = [&](int stage) {
        __half* base = smem + stage * STAGE_ELEMS;
#pragma unroll
        for (int i = 0; i < 4; i++) {
            int id  = t + i * 256;
            int row = id >> 3;
            int col = (id & 7) * 4;
            int off = row * RS + col;
            float4 va = pa[i];
            float4 vb = pb[i];
            uint32_t ah0 = pack_h2(va.x, va.y);
            uint32_t ah1 = pack_h2(va.z, va.w);
            uint32_t al0 = pack_h2_lo(va.x, va.y, ah0);
            uint32_t al1 = pack_h2_lo(va.z, va.w, ah1);
            uint32_t bh0 = pack_h2(vb.x, vb.y);
            uint32_t bh1 = pack_h2(vb.z, vb.w);
            *(uint2*)(base + 0 * SEG + off) = make_uint2(ah0, ah1);
            *(uint2*)(base + 1 * SEG + off) = make_uint2(al0, al1);
            *(uint2*)(base + 2 * SEG + off) = make_uint2(bh0, bh1);
        }
    };

    const int nchunks = Kd / 32;
    gload(0);
    sstore(0);
    __syncthreads();

    for (int c = 0; c < nchunks; c++) {
        const int stage = c & 1;
        if (c + 1 < nchunks) gload((c + 1) * 32);

        const uint32_t sstage = sb + stage * STAGE_BYTES;
        const uint32_t a_base =
            sstage + ((wm + (lane & 15)) * RS + (lane >> 4) * 8) * 2;
        const uint32_t b_base =
            sstage + 2 * SEG * 2 +
            ((wn + (lane & 7)) * RS + (((lane & 15) >> 3) * 8)) * 2;

#pragma unroll
        for (int ks = 0; ks < 2; ks++) {
            uint32_t ah[4][4], al[4][4], bh[4][2];
#pragma unroll
            for (int mt = 0; mt < 4; mt++) {
                uint32_t addr = a_base + (mt * 16 * RS + ks * 16) * 2;
                ldm_x4(ah[mt], addr);
                ldm_x4(al[mt], addr + SEG * 2);
            }
#pragma unroll
            for (int nt = 0; nt < 4; nt++) {
                uint32_t addr = b_base + (nt * 8 * RS + ks * 16) * 2;
                ldm_x2(bh[nt], addr);
            }
#pragma unroll
            for (int mt = 0; mt < 4; mt++)
#pragma unroll
                for (int nt = 0; nt < 4; nt++) {
                    mma_f16(acc[mt][nt], ah[mt], bh[nt]);
                    mma_f16(acc[mt][nt], al[mt], bh[nt]);
                }
        }
        __syncthreads();
        if (c + 1 < nchunks) {
            sstore(stage ^ 1);
            __syncthreads();
        }
    }

    const int r0 = bm + wm + (lane >> 2);
    const int c0 = bn + wn + (lane & 3) * 2;
#pragma unroll
    for (int mt = 0; mt < 4; mt++)
#pragma unroll
        for (int nt = 0; nt < 4; nt++) {
            size_t o0 = (size_t)(r0 + mt * 16) * N + c0 + nt * 8;
            size_t o1 = o0 + (size_t)8 * N;
            if (MODE == 2) {
                *(float2*)(C + o0) = make_float2(acc[mt][nt][0], acc[mt][nt][1]);
                *(float2*)(C + o1) = make_float2(acc[mt][nt][2], acc[mt][nt][3]);
            } else if (MODE == 1) {
                *(uint32_t*)(Ch + o0) = pack_h2(acc[mt][nt][0], acc[mt][nt][1]);
                *(uint32_t*)(Ch + o1) = pack_h2(acc[mt][nt][2], acc[mt][nt][3]);
            } else {
                float v0 = acc[mt][nt][0] * scale;
                float v1 = acc[mt][nt][1] * scale;
                float v2 = acc[mt][nt][2] * scale;
                float v3 = acc[mt][nt][3] * scale;
                uint32_t h01 = pack_h2(v0, v1);
                uint32_t h23 = pack_h2(v2, v3);
                *(uint32_t*)(Ch + o0)  = h01;
                *(uint32_t*)(Chl + o0) = pack_h2_lo(v0, v1, h01);
                *(uint32_t*)(Ch + o1)  = h23;
                *(uint32_t*)(Chl + o1) = pack_h2_lo(v2, v3, h23);
            }
        }
}

__global__ __launch_bounds__(256, 1)
void gemm_q(const float* __restrict__ A, const float* __restrict__ B,
            __half* __restrict__ Ch, __half* __restrict__ Chl) {
    extern __shared__ __half smem[];
    gemm_body<3>(A, B, nullptr, Ch, Chl, QSCALE, S_LEN, DIM, DIM, smem);
}
__global__ __launch_bounds__(256, 1)
void gemm_kv(const float* __restrict__ A, const float* __restrict__ B,
             __half* __restrict__ Ch) {
    extern __shared__ __half smem[];
    gemm_body<1>(A, B, nullptr, Ch, nullptr, 1.0f, S_LEN, DIM, DIM, smem);
}
__global__ __launch_bounds__(256, 1)
void gemm_out(const float* __restrict__ A, const float* __restrict__ B,
              float* __restrict__ C) {
    extern __shared__ __half smem[];
    gemm_body<2>(A, B, C, nullptr, nullptr, 1.0f, S_LEN, DIM, DIM, smem);
}

// ===========================================================================
// Tensor-core causal flash attention, split-KV warp pairs, all-fp16 mma.
// QK: fp16 2-pass (Q hi/lo x K single).  PV: fp16 2-pass (P hi/lo x V single).
// Logits in log2 domain (log2e folded into Q scale) -> exp2f softmax.
// CTA = 128 q rows x 1 head; 512 threads = 8 row-groups x 2 key-halves.
// smem rows (RS2=72 fp16 each):
//   [0..127] Qhi  [128..255] Qlo
//   stage s at 256+s*128:  K(64) V(64)
// ===========================================================================
#define RS2 72
#define ATTN_SMEM (512 * RS2 * 2)   // 73728 bytes
#define MRG_STRIDE 68
#define MRG_GRP (16 * MRG_STRIDE + 32)

__global__ __launch_bounds__(512, 1)
void attn_mma(const __half* __restrict__ Qh, const __half* __restrict__ Ql,
              const __half* __restrict__ K, const __half* __restrict__ V,
              float* __restrict__ Z) {
    extern __shared__ __half sm[];
    const uint32_t sb = smem_u32(sm);
    const int qb   = (int)gridDim.x - 1 - (int)blockIdx.x;  // big tiles first
    const int h    = blockIdx.y;
    const int t    = threadIdx.x;
    const int lane = t & 31;
    const int w    = t >> 5;
    const int g    = w >> 1;      // row group 0..7
    const int hf   = w & 1;       // key half 0/1

    auto issue_kv = [&](int kb, int s) {
#pragma unroll
        for (int i = 0; i < 2; i++) {
            int idx = t + i * 512;
            int mtx = idx >> 9;           // 0=K 1=V
            int r   = (idx >> 3) & 63;
            int c8  = (idx & 7) * 8;
            const __half* src =
                (mtx ? V : K) + (size_t)(kb * 64 + r) * DIM + h * 64 + c8;
            uint32_t dst =
                sb + ((256 + s * 128 + mtx * 64 + r) * RS2 + c8) * 2;
            CP_ASYNC16(dst, src);
        }
    };

    // ---- prologue: Q (hi+lo) + stage 0 K/V ----
    {
#pragma unroll
        for (int i = 0; i < 4; i++) {
            int idx = t + i * 512;
            int buf = idx >> 10;
            int r   = (idx >> 3) & 127;
            int c8  = (idx & 7) * 8;
            const __half* src =
                (buf ? Ql : Qh) + (size_t)(qb * 128 + r) * DIM + h * 64 + c8;
            uint32_t dst = sb + ((buf * 128 + r) * RS2 + c8) * 2;
            CP_ASYNC16(dst, src);
        }
        issue_kv(0, 0);
        CP_COMMIT();
        CP_WAIT0();
    }
    __syncthreads();

    const uint32_t q_base =
        sb + ((g * 16 + (lane & 15)) * RS2 + (lane >> 4) * 8) * 2;

    float o[8][4] = {};
    float m0 = -1e30f, m1 = -1e30f, l0 = 0.f, l1 = 0.f;
    const int row0 = qb * 128 + g * 16 + (lane >> 2);

    const int nkb = 2 * qb + 2;
    for (int kb = 0; kb < nkb; kb++) {
        const int s = kb & 1;
        if (kb + 1 < nkb) { issue_kv(kb + 1, s ^ 1); CP_COMMIT(); }

        const bool active = (kb * 64 + hf * 32 <= qb * 128 + g * 16 + 15);
        if (active) {
            const int KB = 256 + s * 128;        // K rows
            const int VB = KB + 64;              // V rows

            // ---- S = Q K^T on this warp's 32 keys (fp16 2-pass) ----
            float c[4][4] = {};
#pragma unroll
            for (int ks = 0; ks < 4; ks++) {
                uint32_t qhf[4], qlf[4];
                ldm_x4(qhf, q_base + ks * 32);
                ldm_x4(qlf, q_base + ks * 32 + 128 * RS2 * 2);
#pragma unroll
                for (int ntp = 0; ntp < 2; ntp++) {
                    uint32_t fh[4];
                    uint32_t addr = sb +
                        ((KB + hf * 32 + ntp * 16 + (lane & 15)) * RS2 +
                         ks * 16 + (lane >> 4) * 8) * 2;
                    ldm_x4(fh, addr);
                    uint32_t beh[2] = {fh[0], fh[2]};
                    uint32_t boh[2] = {fh[1], fh[3]};
                    mma_f16(c[2 * ntp],     qhf, beh);
                    mma_f16(c[2 * ntp],     qlf, beh);
                    mma_f16(c[2 * ntp + 1], qhf, boh);
                    mma_f16(c[2 * ntp + 1], qlf, boh);
                }
            }

            // ---- causal mask ----
            if (kb * 64 + hf * 32 + 31 > row0) {
                const int colbase = kb * 64 + hf * 32 + (lane & 3) * 2;
#pragma unroll
                for (int nt = 0; nt < 4; nt++) {
                    int cc = colbase + nt * 8;
                    if (cc     > row0)     c[nt][0] = -1e30f;
                    if (cc + 1 > row0)     c[nt][1] = -1e30f;
                    if (cc     > row0 + 8) c[nt][2] = -1e30f;
                    if (cc + 1 > row0 + 8) c[nt][3] = -1e30f;
                }
            }

            // ---- online softmax (log2 domain) ----
            float mx0 = -1e30f, mx1 = -1e30f;
#pragma unroll
            for (int nt = 0; nt < 4; nt++) {
                mx0 = fmaxf(mx0, fmaxf(c[nt][0], c[nt][1]));
                mx1 = fmaxf(mx1, fmaxf(c[nt][2], c[nt][3]));
            }
            mx0 = fmaxf(mx0, __shfl_xor_sync(0xffffffffu, mx0, 1));
            mx0 = fmaxf(mx0, __shfl_xor_sync(0xffffffffu, mx0, 2));
            mx1 = fmaxf(mx1, __shfl_xor_sync(0xffffffffu, mx1, 1));
            mx1 = fmaxf(mx1, __shfl_xor_sync(0xffffffffu, mx1, 2));
            float M0 = fmaxf(m0, mx0);
            float M1 = fmaxf(m1, mx1);
            float sc0 = exp2f(m0 - M0);
            float sc1 = exp2f(m1 - M1);
            m0 = M0; m1 = M1;
            float s0 = 0.f, s1 = 0.f;
#pragma unroll
            for (int nt = 0; nt < 4; nt++) {
                c[nt][0] = exp2f(c[nt][0] - M0);
                c[nt][1] = exp2f(c[nt][1] - M0);
                c[nt][2] = exp2f(c[nt][2] - M1);
                c[nt][3] = exp2f(c[nt][3] - M1);
                s0 += c[nt][0] + c[nt][1];
                s1 += c[nt][2] + c[nt][3];
            }
            s0 += __shfl_xor_sync(0xffffffffu, s0, 1);
            s0 += __shfl_xor_sync(0xffffffffu, s0, 2);
            s1 += __shfl_xor_sync(0xffffffffu, s1, 1);
            s1 += __shfl_xor_sync(0xffffffffu, s1, 2);
            l0 = l0 * sc0 + s0;
            l1 = l1 * sc1 + s1;
#pragma unroll
            for (int nt = 0; nt < 8; nt++) {
                o[nt][0] *= sc0; o[nt][1] *= sc0;
                o[nt][2] *= sc1; o[nt][3] *= sc1;
            }

            // ---- O += P V (fp16 2-pass: P hi/lo, V single) ----
#pragma unroll
            for (int ks = 0; ks < 2; ks++) {
                uint32_t ph[4], pl[4];
                ph[0] = pack_h2(c[2 * ks][0],     c[2 * ks][1]);
                ph[1] = pack_h2(c[2 * ks][2],     c[2 * ks][3]);
                ph[2] = pack_h2(c[2 * ks + 1][0], c[2 * ks + 1][1]);
                ph[3] = pack_h2(c[2 * ks + 1][2], c[2 * ks + 1][3]);
                pl[0] = pack_h2_lo(c[2 * ks][0],     c[2 * ks][1],     ph[0]);
                pl[1] = pack_h2_lo(c[2 * ks][2],     c[2 * ks][3],     ph[1]);
                pl[2] = pack_h2_lo(c[2 * ks + 1][0], c[2 * ks + 1][1], ph[2]);
                pl[3] = pack_h2_lo(c[2 * ks + 1][2], c[2 * ks + 1][3], ph[3]);
#pragma unroll
                for (int ntp = 0; ntp < 4; ntp++) {
                    uint32_t fh[4];
                    uint32_t addr = sb +
                        ((VB + hf * 32 + ks * 16 + (lane & 15)) * RS2 +
                         ntp * 16 + (lane >> 4) * 8) * 2;
                    ldm_x4t(fh, addr);
                    uint32_t veh[2] = {fh[0], fh[1]};
                    uint32_t voh[2] = {fh[2], fh[3]};
                    mma_f16(o[2 * ntp],     ph, veh);
                    mma_f16(o[2 * ntp],     pl, veh);
                    mma_f16(o[2 * ntp + 1], ph, voh);
                    mma_f16(o[2 * ntp + 1], pl, voh);
                }
            }
        }
        if (kb + 1 < nkb) CP_WAIT0();
        __syncthreads();
    }

    // ---- merge warp pairs via smem (hf=1 publishes, hf=0 merges+stores) ----
    float* smf = (float*)sm;
    const int r4 = lane >> 2;
    const int c2 = (lane & 3) * 2;
    if (hf == 1) {
        float* gbuf = smf + g * MRG_GRP;
#pragma unroll
        for (int nt = 0; nt < 8; nt++) {
            float* p0 = gbuf + r4 * MRG_STRIDE + c2 + nt * 8;
            p0[0] = o[nt][0];
            p0[1] = o[nt][1];
            float* p1 = gbuf + (r4 + 8) * MRG_STRIDE + c2 + nt * 8;
            p1[0] = o[nt][2];
            p1[1] = o[nt][3];
        }
        if ((lane & 3) == 0) {
            gbuf[16 * MRG_STRIDE + r4]      = m0;
            gbuf[16 * MRG_STRIDE + 8 + r4]  = m1;
            gbuf[16 * MRG_STRIDE + 16 + r4] = l0;
            gbuf[16 * MRG_STRIDE + 24 + r4] = l1;
        }
    }
    __syncthreads();
    if (hf == 0) {
        float* gbuf = smf + g * MRG_GRP;
        float mb0 = gbuf[16 * MRG_STRIDE + r4];
        float mb1 = gbuf[16 * MRG_STRIDE + 8 + r4];
        float lb0 = gbuf[16 * MRG_STRIDE + 16 + r4];
        float lb1 = gbuf[16 * MRG_STRIDE + 24 + r4];
        float M0 = fmaxf(m0, mb0);
        float M1 = fmaxf(m1, mb1);
        float ea0 = exp2f(m0 - M0), eb0 = exp2f(mb0 - M0);
        float ea1 = exp2f(m1 - M1), eb1 = exp2f(mb1 - M1);
        float inv0 = 1.0f / (l0 * ea0 + lb0 * eb0);
        float inv1 = 1.0f / (l1 * ea1 + lb1 * eb1);
        float* z0 = Z + (size_t)row0 * DIM + h * HD + c2;
#pragma unroll
        for (int nt = 0; nt < 8; nt++) {
            float* p0 = gbuf + r4 * MRG_STRIDE + c2 + nt * 8;
            float* p1 = gbuf + (r4 + 8) * MRG_STRIDE + c2 + nt * 8;
            *(float2*)(z0 + nt * 8) = make_float2(
                (o[nt][0] * ea0 + p0[0] * eb0) * inv0,
                (o[nt][1] * ea0 + p0[1] * eb0) * inv0);
            *(float2*)(z0 + (size_t)8 * DIM + nt * 8) = make_float2(
                (o[nt][2] * ea1 + p1[0] * eb1) * inv1,
                (o[nt][3] * ea1 + p1[1] * eb1) * inv1);
        }
    }
}

// ===========================================================================
extern "C" void kernel_launch(void* const* d_in, const int* in_sizes, int n_in,
                              void* d_out, int out_size) {
    const float* x  = (const float*)d_in[0];
    const float* Wq = (const float*)d_in[1];
    const float* Wk = (const float*)d_in[2];
    const float* Wv = (const float*)d_in[3];
    const float* Wo = (const float*)d_in[4];
    float* out = (float*)d_out;

    __half *dQh, *dQl, *dK, *dV;
    float* dZ;
    cudaGetSymbolAddress((void**)&dQh, g_Qh);
    cudaGetSymbolAddress((void**)&dQl, g_Ql);
    cudaGetSymbolAddress((void**)&dK, g_K);
    cudaGetSymbolAddress((void**)&dV, g_V);
    cudaGetSymbolAddress((void**)&dZ, g_Z);

    cudaFuncSetAttribute(gemm_q,
                         cudaFuncAttributeMaxDynamicSharedMemorySize, GEMM_SMEM);
    cudaFuncSetAttribute(gemm_kv,
                         cudaFuncAttributeMaxDynamicSharedMemorySize, GEMM_SMEM);
    cudaFuncSetAttribute(gemm_out,
                         cudaFuncAttributeMaxDynamicSharedMemorySize, GEMM_SMEM);
    cudaFuncSetAttribute(attn_mma,
                         cudaFuncAttributeMaxDynamicSharedMemorySize, ATTN_SMEM);

    dim3 gproj(DIM / 128, S_LEN / 128);   // (8, 32)
    gemm_q <<<gproj, 256, GEMM_SMEM>>>(x, Wq, dQh, dQl);
    gemm_kv<<<gproj, 256, GEMM_SMEM>>>(x, Wk, dK);
    gemm_kv<<<gproj, 256, GEMM_SMEM>>>(x, Wv, dV);

    attn_mma<<<dim3(S_LEN / 128, NH), 512, ATTN_SMEM>>>(dQh, dQl, dK, dV, dZ);

    gemm_out<<<gproj, 256, GEMM_SMEM>>>(dZ, Wo, out);
}